// round 3
// baseline (speedup 1.0000x reference)
#include <cuda_runtime.h>
#include <cuda_bf16.h>
#include <math.h>

#define NOP     2048
#define NGATES  8192
#define NACT    1024
#define NB      32

#define SMEM_ROWS 54
// dynamic smem layout (bytes)
#define OFF_W    0
#define OFF_H    (SMEM_ROWS * NOP * 2)          // 221184
#define OFF_PART (OFF_H + NOP * 4)              // 229376
#define OFF_XG   (OFF_PART + 2 * 64 * 4)        // 229888
#define OFF_C    (OFF_XG + 64 * 4)              // 230144
#define SMEM_TOTAL (OFF_C + 16 * 4)             // 230208 <= 232448

// ---------------- scratch (static device globals; no runtime allocation) ---
// __align__(16): these are accessed with 8/16-byte vector ops.
__device__ __align__(16) __nv_bfloat16 g_whh[(size_t)NGATES * NOP]; // 32 MB bf16
__device__ __align__(16) float g_xg[NGATES];                        // x_gates
__device__ __align__(16) float g_h[2][NOP];                         // dbl-buffered h
__device__ __align__(16) float g_hall[(size_t)NACT * NOP];          // all h_t (8 MB)
__device__ __align__(16) float g_ent[NACT];
__device__ __align__(16) float g_rein[NACT];
__device__ unsigned g_cnt  = 0;   // barrier counter (reset each barrier)
__device__ unsigned g_flag = 0;   // sense flag (1024 flips -> returns to 0)
__device__ int g_act64 = 0;       // 1 if action buffer is int64, 0 if int32

// ---------------- helpers ---------------------------------------------------
__device__ __forceinline__ float bf_lo(unsigned u) { return __uint_as_float(u << 16); }
__device__ __forceinline__ float bf_hi(unsigned u) { return __uint_as_float(u & 0xffff0000u); }

__device__ __forceinline__ void gbar(int* sense) {
    __syncthreads();
    if (threadIdx.x == 0) {
        unsigned ns = (unsigned)(*sense ^ 1);
        unsigned a;
        asm volatile("atom.release.gpu.global.add.u32 %0, [%1], %2;"
                     : "=r"(a) : "l"(&g_cnt), "r"(1u) : "memory");
        if (a == gridDim.x - 1) {
            asm volatile("st.relaxed.gpu.global.u32 [%0], %1;"
                         :: "l"(&g_cnt), "r"(0u) : "memory");
            asm volatile("st.release.gpu.global.u32 [%0], %1;"
                         :: "l"(&g_flag), "r"(ns) : "memory");
        } else {
            unsigned v;
            do {
                asm volatile("ld.acquire.gpu.global.u32 %0, [%1];"
                             : "=r"(v) : "l"(&g_flag) : "memory");
            } while (v != ns);
        }
    }
    __syncthreads();
    *sense ^= 1;
}

// one row-half dot product: 1024 K-values (32 per lane as 4x uint4 of bf16)
__device__ __forceinline__ float dot_half(const uint4* __restrict__ wp,
                                          const float* __restrict__ hreg,
                                          int g2, int lane) {
    float a0 = 0.f, a1 = 0.f, a2 = 0.f, a3 = 0.f;
#pragma unroll
    for (int m = 0; m < 4; m++) {
        uint4 w = wp[g2 * 128 + m * 32 + lane];
        const float* hr = hreg + m * 8;
        a0 = fmaf(bf_lo(w.x), hr[0], a0);
        a1 = fmaf(bf_hi(w.x), hr[1], a1);
        a2 = fmaf(bf_lo(w.y), hr[2], a2);
        a3 = fmaf(bf_hi(w.y), hr[3], a3);
        a0 = fmaf(bf_lo(w.z), hr[4], a0);
        a1 = fmaf(bf_hi(w.z), hr[5], a1);
        a2 = fmaf(bf_lo(w.w), hr[6], a2);
        a3 = fmaf(bf_hi(w.w), hr[7], a3);
    }
    return (a0 + a1) + (a2 + a3);
}

// ---------------- dtype detect: int64 vs int32 action buffer ----------------
// Reads odd 32-bit words in [1, 511] — in-bounds for BOTH layouts (int32
// layout has 32768 words). int64 little-endian values < 2048 -> all high
// (odd) words are 0. int32 actions are random in [0,2048): P(255 words all
// zero) ~ 2^-2800. Deterministic per input -> graph-safe.
__global__ void detect_act(const int* __restrict__ act_words) {
    __shared__ int any;
    if (threadIdx.x == 0) any = 0;
    __syncthreads();
    for (int i = 1 + 2 * threadIdx.x; i < 512; i += 2 * blockDim.x)
        if (act_words[i] != 0) atomicOr(&any, 1);
    __syncthreads();
    if (threadIdx.x == 0) g_act64 = (any == 0) ? 1 : 0;
}

// ---------------- prep: W_hh fp32 -> bf16 -----------------------------------
__global__ void prep_w(const float* __restrict__ Whh) {
    const int n = NGATES * NOP / 4;
    for (int i = blockIdx.x * blockDim.x + threadIdx.x; i < n;
         i += gridDim.x * blockDim.x) {
        float4 v = reinterpret_cast<const float4*>(Whh)[i];
        unsigned lo = ((unsigned)__bfloat16_as_ushort(__float2bfloat16(v.y)) << 16) |
                       (unsigned)__bfloat16_as_ushort(__float2bfloat16(v.x));
        unsigned hi = ((unsigned)__bfloat16_as_ushort(__float2bfloat16(v.w)) << 16) |
                       (unsigned)__bfloat16_as_ushort(__float2bfloat16(v.z));
        reinterpret_cast<uint2*>(g_whh)[i] = make_uint2(lo, hi);
    }
}

// ---------------- prep: x_gates = rowsum(W_ih)/NOP + b_ih + b_hh ------------
__global__ void prep_xg(const float* __restrict__ Wih,
                        const float* __restrict__ bih,
                        const float* __restrict__ bhh) {
    int warp = (blockIdx.x * blockDim.x + threadIdx.x) >> 5;
    int lane = threadIdx.x & 31;
    if (warp >= NGATES) return;
    const float4* rp = reinterpret_cast<const float4*>(Wih + (size_t)warp * NOP);
    float s = 0.f;
    for (int m = lane; m < NOP / 4; m += 32) {
        float4 v = rp[m];
        s += (v.x + v.y) + (v.z + v.w);
    }
#pragma unroll
    for (int o = 16; o; o >>= 1) s += __shfl_xor_sync(0xffffffffu, s, o);
    if (lane == 0) g_xg[warp] = s * (1.0f / NOP) + bih[warp] + bhh[warp];
}

// ---------------- main persistent LSTM kernel -------------------------------
__global__ void __launch_bounds__(512, 1) lstm_main() {
    extern __shared__ unsigned char smem[];
    __nv_bfloat16* w_s = reinterpret_cast<__nv_bfloat16*>(smem + OFF_W);
    float* h_s  = reinterpret_cast<float*>(smem + OFF_H);    // 2048 floats
    float* part = reinterpret_cast<float*>(smem + OFF_PART); // [2][64]
    float* xg_s = reinterpret_cast<float*>(smem + OFF_XG);   // [64]
    float* c_s  = reinterpret_cast<float*>(smem + OFF_C);    // [16]

    const int tid  = threadIdx.x;
    const int lane = tid & 31;
    const int wid  = tid >> 5;
    const int g2   = wid >> 3;   // K-half (0/1)
    const int ww   = wid & 7;    // warp within K-group

    const int nblk = gridDim.x;
    const int b    = blockIdx.x;
    const int q    = NOP / nblk, r = NOP % nblk;
    const int base = b * q + (b < r ? b : r);
    const int cnt  = q + (b < r ? 1 : 0);
    const int nrows = 4 * cnt;
    const int nsm   = nrows < SMEM_ROWS ? nrows : SMEM_ROWS;

    // load weight slice into smem (bf16 rows, 4 KB each)
    for (int l = wid; l < nsm; l += 16) {
        int j = (l / cnt) * NOP + base + (l % cnt);
        const uint4* src = reinterpret_cast<const uint4*>(g_whh + (size_t)j * NOP);
        uint4* dst = reinterpret_cast<uint4*>(w_s + (size_t)l * NOP);
        for (int m = lane; m < NOP * 2 / 16; m += 32) dst[m] = src[m];
    }
    for (int l = tid; l < nrows; l += blockDim.x) {
        int j = (l / cnt) * NOP + base + (l % cnt);
        xg_s[l] = g_xg[j];
    }
    if (tid < cnt) {
        c_s[tid] = 0.f;
        __stcg(&g_h[0][base + tid], 0.f);
        __threadfence();
    }

    int cur = 0, sense = 0;

    for (int t = 0; t < NACT; ++t) {
        gbar(&sense);  // h(t) for all indices is now globally visible

        // stage full h into smem (bypass L1: written by other SMs)
        {
            const float4* src = reinterpret_cast<const float4*>(g_h[cur]);
            float4* dst = reinterpret_cast<float4*>(h_s);
            for (int i = tid; i < NOP / 4; i += 512) dst[i] = __ldcg(src + i);
        }
        __syncthreads();

        // per-lane register copy of its K-chunk of h (32 values)
        float hreg[32];
        {
            const float4* hs4 = reinterpret_cast<const float4*>(h_s);
#pragma unroll
            for (int m = 0; m < 4; m++) {
                int i0 = g2 * 256 + m * 64 + lane * 2;
                float4 a = hs4[i0];
                float4 c4 = hs4[i0 + 1];
                hreg[m * 8 + 0] = a.x;  hreg[m * 8 + 1] = a.y;
                hreg[m * 8 + 2] = a.z;  hreg[m * 8 + 3] = a.w;
                hreg[m * 8 + 4] = c4.x; hreg[m * 8 + 5] = c4.y;
                hreg[m * 8 + 6] = c4.z; hreg[m * 8 + 7] = c4.w;
            }
        }

        // each warp: rows l = ww, ww+8, ... (its K-half)
        for (int l = ww; l < nrows; l += 8) {
            float acc;
            if (l < SMEM_ROWS) {
                acc = dot_half(reinterpret_cast<const uint4*>(w_s + (size_t)l * NOP),
                               hreg, g2, lane);
            } else {
                int j = (l / cnt) * NOP + base + (l % cnt);
                acc = dot_half(reinterpret_cast<const uint4*>(g_whh + (size_t)j * NOP),
                               hreg, g2, lane);
            }
#pragma unroll
            for (int o = 16; o; o >>= 1) acc += __shfl_xor_sync(0xffffffffu, acc, o);
            if (lane == 0) part[g2 * 64 + l] = acc;
        }
        __syncthreads();

        // cell update for this block's h-indices
        if (tid < cnt) {
            float gv[4];
#pragma unroll
            for (int g = 0; g < 4; ++g) {
                int l = g * cnt + tid;
                gv[g] = part[l] + part[64 + l] + xg_s[l];
            }
            float ii = 1.f / (1.f + expf(-gv[0]));
            float ff = 1.f / (1.f + expf(-gv[1]));
            float gg = tanhf(gv[2]);
            float oo = 1.f / (1.f + expf(-gv[3]));
            float c  = ff * c_s[tid] + ii * gg;
            c_s[tid] = c;
            float h  = oo * tanhf(c);
            __stcg(&g_h[cur ^ 1][base + tid], h);
            g_hall[(size_t)t * NOP + base + tid] = h;
            __threadfence();  // publish before next barrier arrival
        }
        cur ^= 1;
    }
}

// ---------------- epilogue: per-row log-softmax stats ------------------------
__global__ void post_rows(const int* __restrict__ act_words,
                          const float* __restrict__ rewards) {
    __shared__ float row[NOP];
    __shared__ float red[256];
    const int t = blockIdx.x, tid = threadIdx.x;
    const float* src = g_hall + (size_t)t * NOP;
    for (int i = tid; i < NOP; i += 256) row[i] = src[i];
    __syncthreads();

    float m = -1e30f;
    for (int i = tid; i < NOP; i += 256) m = fmaxf(m, row[i]);
    red[tid] = m; __syncthreads();
    for (int s = 128; s; s >>= 1) {
        if (tid < s) red[tid] = fmaxf(red[tid], red[tid + s]);
        __syncthreads();
    }
    m = red[0]; __syncthreads();

    float se = 0.f, sx = 0.f;
    for (int i = tid; i < NOP; i += 256) {
        float x = row[i];
        float e = expf(x - m);
        se += e; sx += e * x;
    }
    red[tid] = se; __syncthreads();
    for (int s = 128; s; s >>= 1) {
        if (tid < s) red[tid] += red[tid + s];
        __syncthreads();
    }
    const float SE = red[0]; __syncthreads();
    red[tid] = sx; __syncthreads();
    for (int s = 128; s; s >>= 1) {
        if (tid < s) red[tid] += red[tid + s];
        __syncthreads();
    }
    const float SX = red[0]; __syncthreads();

    const float lse = m + logf(SE);
    if (tid == 0) g_ent[t] = lse - SX / SE;   // -sum p*logp for this row

    if (tid < 32) {
        // dtype-robust gather: int64 -> low word at 2*idx; int32 -> word at idx
        int flat = tid * NACT + t;
        int a = g_act64 ? act_words[2 * flat] : act_words[flat];
        a = a < 0 ? 0 : (a >= NOP ? NOP - 1 : a);   // defensive clamp
        float lp = row[a] - lse;
        float pr = rewards[tid] * lp;
#pragma unroll
        for (int o = 16; o; o >>= 1) pr += __shfl_xor_sync(0xffffffffu, pr, o);
        if (tid == 0) g_rein[t] = pr;
    }
}

__global__ void post_final(float* __restrict__ out) {
    __shared__ float r1[256], r2[256];
    const int tid = threadIdx.x;
    float se = 0.f, sr = 0.f;
    for (int i = tid; i < NACT; i += 256) { se += g_ent[i]; sr += g_rein[i]; }
    r1[tid] = se; r2[tid] = sr; __syncthreads();
    for (int s = 128; s; s >>= 1) {
        if (tid < s) { r1[tid] += r1[tid + s]; r2[tid] += r2[tid + s]; }
        __syncthreads();
    }
    if (tid == 0) out[0] = (-r2[0] + (float)NB * r1[0]) / (float)NB;
}

// ---------------- launch -----------------------------------------------------
extern "C" void kernel_launch(void* const* d_in, const int* in_sizes, int n_in,
                              void* d_out, int out_size) {
    const float* Wih     = (const float*)d_in[0];
    const float* Whh     = (const float*)d_in[1];
    const float* bih     = (const float*)d_in[2];
    const float* bhh     = (const float*)d_in[3];
    const float* rewards = (const float*)d_in[4];
    const int*   actw    = (const int*)d_in[5];   // int32 or int64 words
    float* out = (float*)d_out;

    int dev = 0;
    cudaGetDevice(&dev);
    int sms = 148;
    cudaDeviceGetAttribute(&sms, cudaDevAttrMultiProcessorCount, dev);
    if (sms < 1) sms = 148;
    // 230 KB smem/block forces 1 CTA/SM, so grid == #SMs is fully resident
    // and the global barrier cannot deadlock.
    cudaFuncSetAttribute(lstm_main, cudaFuncAttributeMaxDynamicSharedMemorySize,
                         SMEM_TOTAL);

    detect_act<<<1, 256>>>(actw);
    prep_w<<<2048, 256>>>(Whh);
    prep_xg<<<1024, 256>>>(Wih, bih, bhh);
    lstm_main<<<sms, 512, SMEM_TOTAL>>>();
    post_rows<<<NACT, 256>>>(actw, rewards);
    post_final<<<1, 256>>>(out);
}

// round 4
// speedup vs baseline: 1.2623x; 1.2623x over previous
#include <cuda_runtime.h>
#include <cuda_bf16.h>
#include <math.h>

#define NOP     2048
#define NGATES  8192
#define NACT    1024
#define NB      32

#define SMEM_ROWS 54
// dynamic smem layout (bytes)
#define OFF_W    0
#define OFF_H    (SMEM_ROWS * NOP * 2)          // 221184
#define OFF_PART (OFF_H + NOP * 4)              // 229376
#define OFF_XG   (OFF_PART + 2 * 64 * 4)        // 229888
#define SMEM_TOTAL (OFF_XG + 64 * 4)            // 230144 <= 232448

// ---------------- scratch (static device globals) ---------------------------
__device__ __align__(16) __nv_bfloat16 g_whh[(size_t)NGATES * NOP]; // 32 MB bf16
__device__ __align__(16) float g_xg[NGATES];
__device__ __align__(16) float g_h[2][NOP];
__device__ __align__(16) float g_hall[(size_t)NACT * NOP];
__device__ __align__(16) float g_ent[NACT];
__device__ __align__(16) float g_rein[NACT];
__device__ unsigned g_cnt  = 0;   // returns to 0 after each barrier
__device__ unsigned g_flag = 0;   // 1024 flips -> returns to 0 (graph-safe)
__device__ int g_act64 = 0;

// ---------------- helpers ---------------------------------------------------
__device__ __forceinline__ float uaf(unsigned u) { return __uint_as_float(u); }

__device__ __forceinline__ float tanh_fast(float x) {
    float y;
    asm("tanh.approx.f32 %0, %1;" : "=f"(y) : "f"(x));
    return y;
}
__device__ __forceinline__ float sigmoid_fast(float x) {
    return 0.5f * tanh_fast(0.5f * x) + 0.5f;
}

__device__ __forceinline__ void bar_arrive(unsigned ns) {
    unsigned a;
    asm volatile("atom.release.gpu.global.add.u32 %0, [%1], %2;"
                 : "=r"(a) : "l"(&g_cnt), "r"(1u) : "memory");
    if (a == gridDim.x - 1) {
        asm volatile("st.relaxed.gpu.global.u32 [%0], %1;"
                     :: "l"(&g_cnt), "r"(0u) : "memory");
        asm volatile("st.release.gpu.global.u32 [%0], %1;"
                     :: "l"(&g_flag), "r"(ns) : "memory");
    }
}
__device__ __forceinline__ void bar_wait(unsigned ns) {
    unsigned v;
    do {
        asm volatile("ld.acquire.gpu.global.u32 %0, [%1];"
                     : "=r"(v) : "l"(&g_flag) : "memory");
    } while (v != ns);
}

// dot of one row-half (1024 K) from 4 uint4 of packed bf16 against hr[32].
// High-half trick: raw u32 reinterpreted as f32 == hi-bf16 value with junk
// low mantissa bits (rel err <= 2^-9, same order as bf16 rounding itself).
__device__ __forceinline__ float dot4(uint4 w0, uint4 w1, uint4 w2, uint4 w3,
                                      const float* __restrict__ hr) {
    float a0 = 0.f, a1 = 0.f, a2 = 0.f, a3 = 0.f;
    const uint4 ww[4] = {w0, w1, w2, w3};
#pragma unroll
    for (int m = 0; m < 4; m++) {
        uint4 w = ww[m];
        const float* h8 = hr + m * 8;
        a0 = fmaf(uaf(w.x << 16), h8[0], a0);
        a1 = fmaf(uaf(w.x),       h8[1], a1);
        a2 = fmaf(uaf(w.y << 16), h8[2], a2);
        a3 = fmaf(uaf(w.y),       h8[3], a3);
        a0 = fmaf(uaf(w.z << 16), h8[4], a0);
        a1 = fmaf(uaf(w.z),       h8[5], a1);
        a2 = fmaf(uaf(w.w << 16), h8[6], a2);
        a3 = fmaf(uaf(w.w),       h8[7], a3);
    }
    return (a0 + a1) + (a2 + a3);
}

// ---------------- action dtype detect (int64 vs int32) ----------------------
__global__ void detect_act(const int* __restrict__ act_words) {
    __shared__ int any;
    if (threadIdx.x == 0) any = 0;
    __syncthreads();
    for (int i = 1 + 2 * threadIdx.x; i < 512; i += 2 * blockDim.x)
        if (act_words[i] != 0) atomicOr(&any, 1);
    __syncthreads();
    if (threadIdx.x == 0) g_act64 = (any == 0) ? 1 : 0;
}

// ---------------- prep: W_hh fp32 -> bf16 -----------------------------------
__global__ void prep_w(const float* __restrict__ Whh) {
    const int n = NGATES * NOP / 4;
    for (int i = blockIdx.x * blockDim.x + threadIdx.x; i < n;
         i += gridDim.x * blockDim.x) {
        float4 v = reinterpret_cast<const float4*>(Whh)[i];
        unsigned lo = ((unsigned)__bfloat16_as_ushort(__float2bfloat16(v.y)) << 16) |
                       (unsigned)__bfloat16_as_ushort(__float2bfloat16(v.x));
        unsigned hi = ((unsigned)__bfloat16_as_ushort(__float2bfloat16(v.w)) << 16) |
                       (unsigned)__bfloat16_as_ushort(__float2bfloat16(v.z));
        reinterpret_cast<uint2*>(g_whh)[i] = make_uint2(lo, hi);
    }
}

// ---------------- prep: x_gates ----------------------------------------------
__global__ void prep_xg(const float* __restrict__ Wih,
                        const float* __restrict__ bih,
                        const float* __restrict__ bhh) {
    int warp = (blockIdx.x * blockDim.x + threadIdx.x) >> 5;
    int lane = threadIdx.x & 31;
    if (warp >= NGATES) return;
    const float4* rp = reinterpret_cast<const float4*>(Wih + (size_t)warp * NOP);
    float s = 0.f;
    for (int m = lane; m < NOP / 4; m += 32) {
        float4 v = rp[m];
        s += (v.x + v.y) + (v.z + v.w);
    }
#pragma unroll
    for (int o = 16; o; o >>= 1) s += __shfl_xor_sync(0xffffffffu, s, o);
    if (lane == 0) g_xg[warp] = s * (1.0f / NOP) + bih[warp] + bhh[warp];
}

// ---------------- main persistent LSTM kernel -------------------------------
__global__ void __launch_bounds__(512, 1) lstm_main() {
    extern __shared__ unsigned char smem[];
    __nv_bfloat16* w_s = reinterpret_cast<__nv_bfloat16*>(smem + OFF_W);
    float* h_s  = reinterpret_cast<float*>(smem + OFF_H);    // 2048 floats
    float* part = reinterpret_cast<float*>(smem + OFF_PART); // [2][64]
    float* xg_s = reinterpret_cast<float*>(smem + OFF_XG);   // [64]

    const int tid  = threadIdx.x;
    const int lane = tid & 31;
    const int wid  = tid >> 5;
    const int g2   = wid >> 3;   // K-half (0/1)
    const int ww   = wid & 7;    // warp within K-group

    const int nblk = gridDim.x;
    const int b    = blockIdx.x;
    const int q    = NOP / nblk, r = NOP % nblk;
    const int base = b * q + (b < r ? b : r);
    const int cnt  = q + (b < r ? 1 : 0);          // <= 14 for >=147 blocks
    const int nrows = 4 * cnt;                      // <= 56
    const int nsm   = nrows < SMEM_ROWS ? nrows : SMEM_ROWS;

    // ---- stage weight slice into smem (rows [0, nsm)) ----
    for (int l = wid; l < nsm; l += 16) {
        int j = (l / cnt) * NOP + base + (l % cnt);
        const uint4* src = reinterpret_cast<const uint4*>(g_whh + (size_t)j * NOP);
        uint4* dst = reinterpret_cast<uint4*>(w_s + (size_t)l * NOP);
        for (int m = lane; m < 256; m += 32) dst[m] = src[m];
    }
    for (int l = tid; l < nrows; l += blockDim.x) {
        int j = (l / cnt) * NOP + base + (l % cnt);
        xg_s[l] = g_xg[j];
    }

    // ---- tail row (iteration 6): l6 = 48+ww; keep in registers if it spills smem
    const int l6 = 48 + ww;
    const bool tail_act = l6 < nrows;
    const bool tail_reg = tail_act && (l6 >= nsm);
    uint4 wr0 = {0,0,0,0}, wr1 = {0,0,0,0}, wr2 = {0,0,0,0}, wr3 = {0,0,0,0};
    if (tail_reg) {
        int j = (l6 / cnt) * NOP + base + (l6 % cnt);
        const uint4* wp = reinterpret_cast<const uint4*>(g_whh + (size_t)j * NOP)
                          + g2 * 128;
        wr0 = wp[lane]; wr1 = wp[32 + lane]; wr2 = wp[64 + lane]; wr3 = wp[96 + lane];
    }

    // ---- publish h(0) = 0 and arrive barrier 0 ----
    float c_reg = 0.f, h_reg = 0.f;     // warp0, lane < cnt
    if (wid == 0) {
        if (lane < cnt) __stcg(&g_h[0][base + lane], 0.f);
        __syncwarp();
        if (lane == 0) { __threadfence(); bar_arrive(1u); }
    }

    int cur = 0;

    for (int t = 0; t < NACT; ++t) {
        // ---- wait for h(t) globally visible (barrier t, sense = 1-(t&1)) ----
        if (tid == 0) bar_wait(1u - (unsigned)(t & 1));
        __syncthreads();

        // store previous step's output (off critical path)
        if (wid == 0 && lane < cnt && t > 0)
            g_hall[(size_t)(t - 1) * NOP + base + lane] = h_reg;

        // ---- stage h(t) into smem (L2, other SMs wrote it) ----
        {
            const float4* src = reinterpret_cast<const float4*>(g_h[cur]);
            reinterpret_cast<float4*>(h_s)[tid] = __ldcg(src + tid);
        }
        __syncthreads();

        // ---- per-lane register chunk of h (32 values of this K-half) ----
        float hreg[32];
        {
            const float4* hs4 = reinterpret_cast<const float4*>(h_s);
#pragma unroll
            for (int m = 0; m < 4; m++) {
                int i0 = g2 * 256 + m * 64 + lane * 2;
                float4 a = hs4[i0];
                float4 c4 = hs4[i0 + 1];
                hreg[m * 8 + 0] = a.x;  hreg[m * 8 + 1] = a.y;
                hreg[m * 8 + 2] = a.z;  hreg[m * 8 + 3] = a.w;
                hreg[m * 8 + 4] = c4.x; hreg[m * 8 + 5] = c4.y;
                hreg[m * 8 + 6] = c4.z; hreg[m * 8 + 7] = c4.w;
            }
        }

        // ---- 6 uniform smem rows + 1 tail row ----
        float s[7];
        const uint4* wbase = reinterpret_cast<const uint4*>(w_s) + g2 * 128 + lane;
#pragma unroll
        for (int i = 0; i < 6; i++) {
            const uint4* wp = wbase + (size_t)(ww + 8 * i) * 256;
            s[i] = dot4(wp[0], wp[32], wp[64], wp[96], hreg);
        }
        if (tail_act) {
            if (tail_reg) {
                s[6] = dot4(wr0, wr1, wr2, wr3, hreg);
            } else {
                const uint4* wp = wbase + (size_t)l6 * 256;
                s[6] = dot4(wp[0], wp[32], wp[64], wp[96], hreg);
            }
        } else s[6] = 0.f;

        // interleaved cross-lane reduction: 7 parallel shfl chains
#pragma unroll
        for (int o = 16; o; o >>= 1) {
#pragma unroll
            for (int i = 0; i < 7; i++)
                s[i] += __shfl_xor_sync(0xffffffffu, s[i], o);
        }
        if (lane == 0) {
#pragma unroll
            for (int i = 0; i < 7; i++) {
                int l = ww + 8 * i;
                if (l < nrows) part[g2 * 64 + l] = s[i];
            }
        }
        __syncthreads();

        // ---- cell update (warp 0), publish h(t+1), arrive ----
        if (wid == 0) {
            if (lane < cnt) {
                float gv0 = part[lane]            + part[64 + lane]            + xg_s[lane];
                float gv1 = part[cnt + lane]      + part[64 + cnt + lane]      + xg_s[cnt + lane];
                float gv2 = part[2 * cnt + lane]  + part[64 + 2 * cnt + lane]  + xg_s[2 * cnt + lane];
                float gv3 = part[3 * cnt + lane]  + part[64 + 3 * cnt + lane]  + xg_s[3 * cnt + lane];
                float ii = sigmoid_fast(gv0);
                float ff = sigmoid_fast(gv1);
                float gg = tanh_fast(gv2);
                float oo = sigmoid_fast(gv3);
                c_reg = ff * c_reg + ii * gg;
                h_reg = oo * tanh_fast(c_reg);
                __stcg(&g_h[cur ^ 1][base + lane], h_reg);
            }
            __syncwarp();
            if (lane == 0 && t + 1 < NACT) {
                __threadfence();
                bar_arrive(1u - (unsigned)((t + 1) & 1));
            }
        }
        cur ^= 1;
    }

    // final output row
    if (wid == 0 && lane < cnt)
        g_hall[(size_t)(NACT - 1) * NOP + base + lane] = h_reg;
}

// ---------------- epilogue ----------------------------------------------------
__global__ void post_rows(const int* __restrict__ act_words,
                          const float* __restrict__ rewards) {
    __shared__ float row[NOP];
    __shared__ float red[256];
    const int t = blockIdx.x, tid = threadIdx.x;
    const float* src = g_hall + (size_t)t * NOP;
    for (int i = tid; i < NOP; i += 256) row[i] = src[i];
    __syncthreads();

    float m = -1e30f;
    for (int i = tid; i < NOP; i += 256) m = fmaxf(m, row[i]);
    red[tid] = m; __syncthreads();
    for (int s = 128; s; s >>= 1) {
        if (tid < s) red[tid] = fmaxf(red[tid], red[tid + s]);
        __syncthreads();
    }
    m = red[0]; __syncthreads();

    float se = 0.f, sx = 0.f;
    for (int i = tid; i < NOP; i += 256) {
        float x = row[i];
        float e = expf(x - m);
        se += e; sx += e * x;
    }
    red[tid] = se; __syncthreads();
    for (int s = 128; s; s >>= 1) {
        if (tid < s) red[tid] += red[tid + s];
        __syncthreads();
    }
    const float SE = red[0]; __syncthreads();
    red[tid] = sx; __syncthreads();
    for (int s = 128; s; s >>= 1) {
        if (tid < s) red[tid] += red[tid + s];
        __syncthreads();
    }
    const float SX = red[0]; __syncthreads();

    const float lse = m + logf(SE);
    if (tid == 0) g_ent[t] = lse - SX / SE;

    if (tid < 32) {
        int flat = tid * NACT + t;
        int a = g_act64 ? act_words[2 * flat] : act_words[flat];
        a = a < 0 ? 0 : (a >= NOP ? NOP - 1 : a);
        float lp = row[a] - lse;
        float pr = rewards[tid] * lp;
#pragma unroll
        for (int o = 16; o; o >>= 1) pr += __shfl_xor_sync(0xffffffffu, pr, o);
        if (tid == 0) g_rein[t] = pr;
    }
}

__global__ void post_final(float* __restrict__ out) {
    __shared__ float r1[256], r2[256];
    const int tid = threadIdx.x;
    float se = 0.f, sr = 0.f;
    for (int i = tid; i < NACT; i += 256) { se += g_ent[i]; sr += g_rein[i]; }
    r1[tid] = se; r2[tid] = sr; __syncthreads();
    for (int s = 128; s; s >>= 1) {
        if (tid < s) { r1[tid] += r1[tid + s]; r2[tid] += r2[tid + s]; }
        __syncthreads();
    }
    if (tid == 0) out[0] = (-r2[0] + (float)NB * r1[0]) / (float)NB;
}

// ---------------- launch -------------------------------------------------------
extern "C" void kernel_launch(void* const* d_in, const int* in_sizes, int n_in,
                              void* d_out, int out_size) {
    const float* Wih     = (const float*)d_in[0];
    const float* Whh     = (const float*)d_in[1];
    const float* bih     = (const float*)d_in[2];
    const float* bhh     = (const float*)d_in[3];
    const float* rewards = (const float*)d_in[4];
    const int*   actw    = (const int*)d_in[5];
    float* out = (float*)d_out;

    int dev = 0;
    cudaGetDevice(&dev);
    int sms = 148;
    cudaDeviceGetAttribute(&sms, cudaDevAttrMultiProcessorCount, dev);
    if (sms < 147) sms = 148;   // need cnt <= 14 (smem 54 rows + 2 reg rows)
    cudaFuncSetAttribute(lstm_main, cudaFuncAttributeMaxDynamicSharedMemorySize,
                         SMEM_TOTAL);

    detect_act<<<1, 256>>>(actw);
    prep_w<<<2048, 256>>>(Whh);
    prep_xg<<<1024, 256>>>(Wih, bih, bhh);
    lstm_main<<<sms, 512, SMEM_TOTAL>>>();
    post_rows<<<NACT, 256>>>(actw, rewards);
    post_final<<<1, 256>>>(out);
}